// round 7
// baseline (speedup 1.0000x reference)
#include <cuda_runtime.h>
#include <math.h>

#define T_  1024
#define B_  2
#define E_  1024
#define H_  16
#define D_  64
#define TB_ 2048
#define RB_ 4094

// ---------------- scratch ----------------
__device__ float g_Win [3 * E_ * E_];
__device__ float g_Wpos[E_ * E_];
__device__ float g_Wout[E_ * E_];
__device__ float g_bin [3 * E_];
__device__ float g_bpos[E_];
__device__ float g_bout[E_];
__device__ float g_rw  [E_];
__device__ float g_rr  [E_];
__device__ float g_qkv [TB_ * 3 * E_];
__device__ float g_r   [RB_ * E_];
__device__ float g_att [TB_ * E_];

// ---------------- tf32 helpers ----------------
__device__ __forceinline__ unsigned f2tf(float f) {
    unsigned r; asm("cvt.rna.tf32.f32 %0, %1;" : "=r"(r) : "f"(f)); return r;
}
__device__ __forceinline__ void split2(float v, float& hi, float& lo) {
    hi = __uint_as_float(f2tf(v));
    lo = __uint_as_float(f2tf(v - hi));
}
__device__ __forceinline__ void mma8(float* c, const float* a, const float* b) {
    asm volatile("mma.sync.aligned.m16n8k8.row.col.f32.tf32.tf32.f32 "
                 "{%0,%1,%2,%3},{%4,%5,%6,%7},{%8,%9},{%0,%1,%2,%3};"
                 : "+f"(c[0]), "+f"(c[1]), "+f"(c[2]), "+f"(c[3])
                 : "r"(__float_as_uint(a[0])), "r"(__float_as_uint(a[1])),
                   "r"(__float_as_uint(a[2])), "r"(__float_as_uint(a[3])),
                   "r"(__float_as_uint(b[0])), "r"(__float_as_uint(b[1])));
}
__device__ __forceinline__ void mma3(float* c, const float* ah, const float* al,
                                     const float* bh, const float* bl) {
    mma8(c, ah, bh);
    mma8(c, ah, bl);
    mma8(c, al, bh);
}

// ---------------- fused hypernet ----------------
#define HN0 3145728
#define HN1 (HN0 + 1048576)
#define HN2 (HN1 + 1048576)
#define HN3 (HN2 + 3072)
#define HN4 (HN3 + 1024)
#define HN5 (HN4 + 1024)
#define HN6 (HN5 + 1024)
#define HN7 (HN6 + 1024)

__global__ __launch_bounds__(256) void hyper_all(
    const float* __restrict__ w_in,  const float* __restrict__ w_pos,
    const float* __restrict__ w_out, const float* __restrict__ b_in,
    const float* __restrict__ b_pos, const float* __restrict__ b_out,
    const float* __restrict__ rwb,   const float* __restrict__ rrb,
    const float* __restrict__ f,
    float* __restrict__ oWin,  float* __restrict__ oWpos,
    float* __restrict__ oWout, float* __restrict__ obin,
    float* __restrict__ obpos, float* __restrict__ obout,
    float* __restrict__ orw,   float* __restrict__ orr)
{
    int idx = blockIdx.x * blockDim.x + threadIdx.x;
    if (idx >= HN7) return;
    const float* src; float* dst; int off;
    if      (idx < HN0) { src = w_in;  dst = oWin;  off = idx; }
    else if (idx < HN1) { src = w_pos; dst = oWpos; off = idx - HN0; }
    else if (idx < HN2) { src = w_out; dst = oWout; off = idx - HN1; }
    else if (idx < HN3) { src = b_in;  dst = obin;  off = idx - HN2; }
    else if (idx < HN4) { src = b_pos; dst = obpos; off = idx - HN3; }
    else if (idx < HN5) { src = b_out; dst = obout; off = idx - HN4; }
    else if (idx < HN6) { src = rwb;   dst = orw;   off = idx - HN5; }
    else                { src = rrb;   dst = orr;   off = idx - HN6; }
    const float4* wp = (const float4*)(src + (size_t)off * 8);
    float4 a = wp[0], b = wp[1];
    float4 f0 = *(const float4*)f;
    float4 f1 = *(const float4*)(f + 4);
    dst[off] = a.x*f0.x + a.y*f0.y + a.z*f0.z + a.w*f0.w
             + b.x*f1.x + b.y*f1.y + b.z*f1.z + b.w*f1.w;
}

// ---------------- 3xtf32 NT GEMM (unchanged) -----------------------------------
#define GA_H 0
#define GA_L 4608
#define GB_H 9216
#define GB_L 13824
#define GEMM_SMEM (18432 * 4)

__global__ __launch_bounds__(256) void gemm3(const float* __restrict__ A,
                                             const float* __restrict__ Bm,
                                             const float* __restrict__ bias,
                                             float* __restrict__ C,
                                             int M, int N, int K)
{
    extern __shared__ float sm[];
    int bm = blockIdx.y * 128, bn = blockIdx.x * 128;
    int tid = threadIdx.x;
    int w = tid >> 5, lane = tid & 31;
    int g = lane >> 2, tg = lane & 3;
    int wm = w & 1, wn = w >> 1;
    float acc[4][4][4] = {};

    for (int k0 = 0; k0 < K; k0 += 32) {
#pragma unroll
        for (int it = 0; it < 4; it++) {
            int t = tid + 256 * it;
            int row = t >> 3, kq = (t & 7) << 2;
            int m = bm + row;
            float4 av = (m < M) ? *(const float4*)(A + (size_t)m * K + k0 + kq)
                                : make_float4(0.f, 0.f, 0.f, 0.f);
            float4 ah, al;
            split2(av.x, ah.x, al.x); split2(av.y, ah.y, al.y);
            split2(av.z, ah.z, al.z); split2(av.w, ah.w, al.w);
            *(float4*)&sm[GA_H + row * 36 + kq] = ah;
            *(float4*)&sm[GA_L + row * 36 + kq] = al;
            float4 bv = *(const float4*)(Bm + (size_t)(bn + row) * K + k0 + kq);
            float4 bh, bl;
            split2(bv.x, bh.x, bl.x); split2(bv.y, bh.y, bl.y);
            split2(bv.z, bh.z, bl.z); split2(bv.w, bh.w, bl.w);
            *(float4*)&sm[GB_H + row * 36 + kq] = bh;
            *(float4*)&sm[GB_L + row * 36 + kq] = bl;
        }
        __syncthreads();
#pragma unroll
        for (int ks = 0; ks < 4; ks++) {
            float ah[4][4], al[4][4], bh[4][2], bl[4][2];
#pragma unroll
            for (int mi = 0; mi < 4; mi++) {
                int r0 = (wm * 64 + mi * 16 + g) * 36 + ks * 8 + tg;
                ah[mi][0] = sm[GA_H + r0];
                ah[mi][1] = sm[GA_H + r0 + 8 * 36];
                ah[mi][2] = sm[GA_H + r0 + 4];
                ah[mi][3] = sm[GA_H + r0 + 8 * 36 + 4];
                al[mi][0] = sm[GA_L + r0];
                al[mi][1] = sm[GA_L + r0 + 8 * 36];
                al[mi][2] = sm[GA_L + r0 + 4];
                al[mi][3] = sm[GA_L + r0 + 8 * 36 + 4];
            }
#pragma unroll
            for (int ni = 0; ni < 4; ni++) {
                int r0 = (wn * 32 + ni * 8 + g) * 36 + ks * 8 + tg;
                bh[ni][0] = sm[GB_H + r0];
                bh[ni][1] = sm[GB_H + r0 + 4];
                bl[ni][0] = sm[GB_L + r0];
                bl[ni][1] = sm[GB_L + r0 + 4];
            }
#pragma unroll
            for (int mi = 0; mi < 4; mi++)
#pragma unroll
                for (int ni = 0; ni < 4; ni++)
                    mma3(acc[mi][ni], ah[mi], al[mi], bh[ni], bl[ni]);
        }
        __syncthreads();
    }

#pragma unroll
    for (int mi = 0; mi < 4; mi++)
#pragma unroll
        for (int ni = 0; ni < 4; ni++) {
            int m0 = bm + wm * 64 + mi * 16 + g;
            int n0 = bn + wn * 32 + ni * 8 + tg * 2;
            float bb0 = bias[n0], bb1 = bias[n0 + 1];
            if (m0 < M) {
                float2 o = {acc[mi][ni][0] + bb0, acc[mi][ni][1] + bb1};
                *(float2*)(C + (size_t)m0 * N + n0) = o;
            }
            if (m0 + 8 < M) {
                float2 o = {acc[mi][ni][2] + bb0, acc[mi][ni][3] + bb1};
                *(float2*)(C + (size_t)(m0 + 8) * N + n0) = o;
            }
        }
}

// ---------------- fused attention, i-tile 32, 2 CTAs/SM ------------------------
// hi/lo interleaved smem: element (row,k) -> [row*40 + 2k] = hi, +1 = lo.
// Stride 40 floats => float2 accesses conflict-free (stride/2 = 20 ≡ 4 mod 16).
#define AQW  0
#define AQR  1280
#define AK   2560
#define AR   7680
#define AG   0
#define AP   0
#define AV   4224
#define ARMX 14080
#define ARSM 14208
#define ATTN_SMEM (14336 * 4)
#define SC_ 0.125f

__global__ __launch_bounds__(256, 2) void attn_fused(const float* __restrict__ qkv,
                                                     const float* __restrict__ rproj,
                                                     const float* __restrict__ rw,
                                                     const float* __restrict__ rr,
                                                     float* __restrict__ att)
{
    extern __shared__ float sm[];
    const int bh = blockIdx.y;
    const int b = bh / H_, h = bh % H_;
    const int i0 = blockIdx.x * 32;
    const int tid = threadIdx.x;
    const int w = tid >> 5, lane = tid & 31;
    const int g = lane >> 2, tg = lane & 3;
    const int wi = w >> 2, wj = w & 3;   // wi in {0,1}, wj in {0..3}

    float m_run[2] = {-1e30f, -1e30f};
    float l_run[2] = {0.f, 0.f};
    float accO[2][4] = {};

    for (int j0 = 0; j0 < T_; j0 += 128) {
        const int pmin = j0 - i0 + (T_ - 32);
        float accA[4][4] = {};
        float accG[5][4] = {};

        for (int c = 0; c < 4; c++) {
            const int col0 = h * D_ + c * 16;
            __syncthreads();
            // q+rw / q+rr: 32 rows x 16 k (threads < 128)
            if (tid < 128) {
                int il = tid >> 2, kq = (tid & 3) << 2;
                float4 qv = *(const float4*)(qkv + (size_t)((i0 + il) * B_ + b) * (3 * E_) + col0 + kq);
                float4 rwv = *(const float4*)(rw + col0 + kq);
                float4 rrv = *(const float4*)(rr + col0 + kq);
                float h0,l0,h1,l1,h2,l2,h3,l3;
                split2(qv.x + rwv.x, h0, l0); split2(qv.y + rwv.y, h1, l1);
                split2(qv.z + rwv.z, h2, l2); split2(qv.w + rwv.w, h3, l3);
                float4 w0 = {h0, l0, h1, l1}, w1 = {h2, l2, h3, l3};
                *(float4*)&sm[AQW + il * 40 + kq * 2]     = w0;
                *(float4*)&sm[AQW + il * 40 + kq * 2 + 4] = w1;
                split2(qv.x + rrv.x, h0, l0); split2(qv.y + rrv.y, h1, l1);
                split2(qv.z + rrv.z, h2, l2); split2(qv.w + rrv.w, h3, l3);
                float4 r0 = {h0, l0, h1, l1}, r1 = {h2, l2, h3, l3};
                *(float4*)&sm[AQR + il * 40 + kq * 2]     = r0;
                *(float4*)&sm[AQR + il * 40 + kq * 2 + 4] = r1;
            }
            // k: 128 rows x 16 k
#pragma unroll
            for (int it = 0; it < 2; it++) {
                int t = tid + 256 * it;
                int il = t >> 2, kq = (t & 3) << 2;
                float4 kv = *(const float4*)(qkv + (size_t)((j0 + il) * B_ + b) * (3 * E_) + E_ + col0 + kq);
                float h0,l0,h1,l1,h2,l2,h3,l3;
                split2(kv.x, h0, l0); split2(kv.y, h1, l1);
                split2(kv.z, h2, l2); split2(kv.w, h3, l3);
                float4 k0 = {h0, l0, h1, l1}, k1 = {h2, l2, h3, l3};
                *(float4*)&sm[AK + il * 40 + kq * 2]     = k0;
                *(float4*)&sm[AK + il * 40 + kq * 2 + 4] = k1;
            }
            // r window: 159 real rows + 1 zero (160 rows x 16 k)
#pragma unroll
            for (int it = 0; it < 3; it++) {
                int t = tid + 256 * it;
                if (t < 640) {
                    int pl = t >> 2, kq = (t & 3) << 2;
                    float4 rv = (pl < 159)
                        ? *(const float4*)(rproj + (size_t)((pmin + pl) * B_ + b) * E_ + col0 + kq)
                        : make_float4(0.f, 0.f, 0.f, 0.f);
                    float h0,l0,h1,l1,h2,l2,h3,l3;
                    split2(rv.x, h0, l0); split2(rv.y, h1, l1);
                    split2(rv.z, h2, l2); split2(rv.w, h3, l3);
                    float4 r0 = {h0, l0, h1, l1}, r1 = {h2, l2, h3, l3};
                    *(float4*)&sm[AR + pl * 40 + kq * 2]     = r0;
                    *(float4*)&sm[AR + pl * 40 + kq * 2 + 4] = r1;
                }
            }
            __syncthreads();
#pragma unroll
            for (int ks = 0; ks < 2; ks++) {
                float aW[4], aWl[4], aR_[4], aRl[4];
                int ra = (wi * 16 + g) * 40 + (ks * 8 + tg) * 2;
                {
                    float2 t0 = *(float2*)&sm[AQW + ra];
                    float2 t1 = *(float2*)&sm[AQW + ra + 8 * 40];
                    float2 t2 = *(float2*)&sm[AQW + ra + 8];
                    float2 t3 = *(float2*)&sm[AQW + ra + 8 * 40 + 8];
                    aW[0] = t0.x; aWl[0] = t0.y; aW[1] = t1.x; aWl[1] = t1.y;
                    aW[2] = t2.x; aWl[2] = t2.y; aW[3] = t3.x; aWl[3] = t3.y;
                }
                {
                    float2 t0 = *(float2*)&sm[AQR + ra];
                    float2 t1 = *(float2*)&sm[AQR + ra + 8 * 40];
                    float2 t2 = *(float2*)&sm[AQR + ra + 8];
                    float2 t3 = *(float2*)&sm[AQR + ra + 8 * 40 + 8];
                    aR_[0] = t0.x; aRl[0] = t0.y; aR_[1] = t1.x; aRl[1] = t1.y;
                    aR_[2] = t2.x; aRl[2] = t2.y; aR_[3] = t3.x; aRl[3] = t3.y;
                }
#pragma unroll
                for (int nj = 0; nj < 4; nj++) {
                    int rb = (wj * 32 + nj * 8 + g) * 40 + (ks * 8 + tg) * 2;
                    float2 b0 = *(float2*)&sm[AK + rb];
                    float2 b1 = *(float2*)&sm[AK + rb + 8];
                    float bhf[2] = {b0.x, b1.x}, blf[2] = {b0.y, b1.y};
                    mma3(accA[nj], aW, aWl, bhf, blf);
                }
#pragma unroll
                for (int ng = 0; ng < 5; ng++) {
                    int rb = (wj * 40 + ng * 8 + g) * 40 + (ks * 8 + tg) * 2;
                    float2 b0 = *(float2*)&sm[AR + rb];
                    float2 b1 = *(float2*)&sm[AR + rb + 8];
                    float bhf[2] = {b0.x, b1.x}, blf[2] = {b0.y, b1.y};
                    mma3(accG[ng], aR_, aRl, bhf, blf);
                }
            }
        }
        __syncthreads();

        // stage G[32][164] (aliases stage region)
#pragma unroll
        for (int ng = 0; ng < 5; ng++) {
            int row = wi * 16 + g;
            int cc = wj * 40 + ng * 8 + tg * 2;
            sm[AG + row * 164 + cc]           = accG[ng][0];
            sm[AG + row * 164 + cc + 1]       = accG[ng][1];
            sm[AG + (row + 8) * 164 + cc]     = accG[ng][2];
            sm[AG + (row + 8) * 164 + cc + 1] = accG[ng][3];
        }
        __syncthreads();

        // S = accA + shifted G, per-row max
        float tmax[2] = {-1e30f, -1e30f};
#pragma unroll
        for (int nj = 0; nj < 4; nj++) {
            int il = wi * 16 + g;
            int jl = wj * 32 + nj * 8 + tg * 2;
            int il2 = il + 8;
            accA[nj][0] += sm[AG + il * 164 + (jl - il + 31)];
            accA[nj][1] += sm[AG + il * 164 + (jl + 1 - il + 31)];
            accA[nj][2] += sm[AG + il2 * 164 + (jl - il2 + 31)];
            accA[nj][3] += sm[AG + il2 * 164 + (jl + 1 - il2 + 31)];
            tmax[0] = fmaxf(tmax[0], fmaxf(accA[nj][0], accA[nj][1]));
            tmax[1] = fmaxf(tmax[1], fmaxf(accA[nj][2], accA[nj][3]));
        }
#pragma unroll
        for (int rp = 0; rp < 2; rp++) {
            float v = tmax[rp];
            v = fmaxf(v, __shfl_xor_sync(0xffffffffu, v, 1));
            v = fmaxf(v, __shfl_xor_sync(0xffffffffu, v, 2));
            tmax[rp] = v;
        }
        if (tg == 0) {
#pragma unroll
            for (int rp = 0; rp < 2; rp++) {
                int row = wi * 16 + g + rp * 8;
                sm[ARMX + row * 4 + wj] = tmax[rp];
            }
        }
        __syncthreads();

        float mnew[2], fsc[2];
#pragma unroll
        for (int rp = 0; rp < 2; rp++) {
            int row = wi * 16 + g + rp * 8;
            float mt = fmaxf(fmaxf(sm[ARMX + row * 4 + 0], sm[ARMX + row * 4 + 1]),
                             fmaxf(sm[ARMX + row * 4 + 2], sm[ARMX + row * 4 + 3]));
            mnew[rp] = fmaxf(m_run[rp], mt);
            fsc[rp] = __expf((m_run[rp] - mnew[rp]) * SC_);
        }

        float tsum[2] = {0.f, 0.f};
#pragma unroll
        for (int nj = 0; nj < 4; nj++) {
            int il = wi * 16 + g;
            int jl = wj * 32 + nj * 8 + tg * 2;
            float p0 = __expf((accA[nj][0] - mnew[0]) * SC_);
            float p1 = __expf((accA[nj][1] - mnew[0]) * SC_);
            float p2 = __expf((accA[nj][2] - mnew[1]) * SC_);
            float p3 = __expf((accA[nj][3] - mnew[1]) * SC_);
            tsum[0] += p0 + p1;
            tsum[1] += p2 + p3;
            sm[AP + il * 132 + jl]           = __uint_as_float(f2tf(p0));
            sm[AP + il * 132 + jl + 1]       = __uint_as_float(f2tf(p1));
            sm[AP + (il + 8) * 132 + jl]     = __uint_as_float(f2tf(p2));
            sm[AP + (il + 8) * 132 + jl + 1] = __uint_as_float(f2tf(p3));
        }
#pragma unroll
        for (int rp = 0; rp < 2; rp++) {
            float v = tsum[rp];
            v += __shfl_xor_sync(0xffffffffu, v, 1);
            v += __shfl_xor_sync(0xffffffffu, v, 2);
            tsum[rp] = v;
        }
        if (tg == 0) {
#pragma unroll
            for (int rp = 0; rp < 2; rp++) {
                int row = wi * 16 + g + rp * 8;
                sm[ARSM + row * 4 + wj] = tsum[rp];
            }
        }
        __syncthreads();

#pragma unroll
        for (int rp = 0; rp < 2; rp++) {
            int row = wi * 16 + g + rp * 8;
            float lt = sm[ARSM + row * 4 + 0] + sm[ARSM + row * 4 + 1]
                     + sm[ARSM + row * 4 + 2] + sm[ARSM + row * 4 + 3];
            l_run[rp] = l_run[rp] * fsc[rp] + lt;
            m_run[rp] = mnew[rp];
        }
#pragma unroll
        for (int nd = 0; nd < 2; nd++) {
            accO[nd][0] *= fsc[0];
            accO[nd][1] *= fsc[0];
            accO[nd][2] *= fsc[1];
            accO[nd][3] *= fsc[1];
        }

        // PV: accO += P_hi * (V_hi + V_lo); V interleaved stride 136
        for (int jc = 0; jc < 2; jc++) {
            __syncthreads();
#pragma unroll
            for (int it = 0; it < 4; it++) {
                int t = tid + 256 * it;
                int row = t >> 4, dq = (t & 15) << 2;
                float4 vv = *(const float4*)(qkv + (size_t)((j0 + jc * 64 + row) * B_ + b) * (3 * E_)
                                             + 2 * E_ + h * D_ + dq);
                float h0,l0,h1,l1,h2,l2,h3,l3;
                split2(vv.x, h0, l0); split2(vv.y, h1, l1);
                split2(vv.z, h2, l2); split2(vv.w, h3, l3);
                float4 v0 = {h0, l0, h1, l1}, v1 = {h2, l2, h3, l3};
                *(float4*)&sm[AV + row * 136 + dq * 2]     = v0;
                *(float4*)&sm[AV + row * 136 + dq * 2 + 4] = v1;
            }
            __syncthreads();
#pragma unroll
            for (int ks = 0; ks < 8; ks++) {
                float a[4];
                int ra = (wi * 16 + g) * 132 + jc * 64 + ks * 8 + tg;
                a[0] = sm[AP + ra];
                a[1] = sm[AP + ra + 8 * 132];
                a[2] = sm[AP + ra + 4];
                a[3] = sm[AP + ra + 8 * 132 + 4];
#pragma unroll
                for (int nd = 0; nd < 2; nd++) {
                    int cb = (wj * 16 + nd * 8 + g) * 2;
                    float2 v0 = *(float2*)&sm[AV + (ks * 8 + tg) * 136 + cb];
                    float2 v1 = *(float2*)&sm[AV + (ks * 8 + tg + 4) * 136 + cb];
                    float vh[2] = {v0.x, v1.x}, vl[2] = {v0.y, v1.y};
                    mma8(accO[nd], a, vh);
                    mma8(accO[nd], a, vl);
                }
            }
        }
    }

    // epilogue
    float inv[2];
#pragma unroll
    for (int rp = 0; rp < 2; rp++) inv[rp] = 1.0f / l_run[rp];
#pragma unroll
    for (int nd = 0; nd < 2; nd++) {
        int row = wi * 16 + g;
        int col = h * D_ + wj * 16 + nd * 8 + tg * 2;
        float2 o0 = {accO[nd][0] * inv[0], accO[nd][1] * inv[0]};
        float2 o1 = {accO[nd][2] * inv[1], accO[nd][3] * inv[1]};
        *(float2*)(att + (size_t)((i0 + row) * B_ + b) * E_ + col) = o0;
        *(float2*)(att + (size_t)((i0 + row + 8) * B_ + b) * E_ + col) = o1;
    }
}

// ---------------- launch ----------------
extern "C" void kernel_launch(void* const* d_in, const int* in_sizes, int n_in,
                              void* d_out, int out_size)
{
    (void)in_sizes; (void)n_in; (void)out_size;
    const float* input  = (const float*)d_in[0];
    const float* pos    = (const float*)d_in[1];
    const float* factor = (const float*)d_in[2];
    const float* w_in   = (const float*)d_in[3];
    const float* w_pos  = (const float*)d_in[4];
    const float* w_out  = (const float*)d_in[5];
    const float* bw_in  = (const float*)d_in[6];
    const float* bw_pos = (const float*)d_in[7];
    const float* bw_out = (const float*)d_in[8];
    const float* rwb    = (const float*)d_in[9];
    const float* rrb    = (const float*)d_in[10];

    float *pWin, *pWpos, *pWout, *pbin, *pbpos, *pbout, *prw, *prr,
          *pqkv, *pr, *patt;
    cudaGetSymbolAddress((void**)&pWin,  g_Win);
    cudaGetSymbolAddress((void**)&pWpos, g_Wpos);
    cudaGetSymbolAddress((void**)&pWout, g_Wout);
    cudaGetSymbolAddress((void**)&pbin,  g_bin);
    cudaGetSymbolAddress((void**)&pbpos, g_bpos);
    cudaGetSymbolAddress((void**)&pbout, g_bout);
    cudaGetSymbolAddress((void**)&prw,   g_rw);
    cudaGetSymbolAddress((void**)&prr,   g_rr);
    cudaGetSymbolAddress((void**)&pqkv,  g_qkv);
    cudaGetSymbolAddress((void**)&pr,    g_r);
    cudaGetSymbolAddress((void**)&patt,  g_att);

    cudaFuncSetAttribute(gemm3,      cudaFuncAttributeMaxDynamicSharedMemorySize, GEMM_SMEM);
    cudaFuncSetAttribute(attn_fused, cudaFuncAttributeMaxDynamicSharedMemorySize, ATTN_SMEM);

    // 1) hypernet
    hyper_all<<<(HN7 + 255) / 256, 256>>>(w_in, w_pos, w_out, bw_in, bw_pos, bw_out,
                                          rwb, rrb, factor,
                                          pWin, pWpos, pWout, pbin, pbpos, pbout, prw, prr);

    // 2) projections (3xtf32)
    gemm3<<<dim3(3 * E_ / 128, TB_ / 128), 256, GEMM_SMEM>>>(input, pWin, pbin, pqkv, TB_, 3 * E_, E_);
    gemm3<<<dim3(E_ / 128, (RB_ + 127) / 128), 256, GEMM_SMEM>>>(pos, pWpos, pbpos, pr, RB_, E_, E_);

    // 3) fused attention (i-tile 32, 2 CTAs/SM)
    attn_fused<<<dim3(T_ / 32, B_ * H_), 256, ATTN_SMEM>>>(pqkv, pr, prw, prr, patt);

    // 4) output projection -> d_out
    gemm3<<<dim3(E_ / 128, TB_ / 128), 256, GEMM_SMEM>>>(patt, pWout, pbout, (float*)d_out, TB_, E_, E_);
}